// round 16
// baseline (speedup 1.0000x reference)
#include <cuda_runtime.h>
#include <cuda_fp16.h>
#include <cstdint>
#include <cstddef>

// Problem constants
#define NN    100000
#define INC   512
#define HIDC  256
#define OUTC  32
#define EE    1600000
#define KIT   5
#define LAM1  3.0f
#define GAMMA 0.25f      // 1/(1+LAM2), LAM2=3
#define BETA  2.0f       // 1/(2*GAMMA)

// ---------------- device scratch (static: no allocations allowed) ----------
__device__ float  g_h1[(size_t)NN * HIDC];    // relu(x@W1+b1)          102.4 MB
__device__ float  g_hg[(size_t)NN * OUTC];    // gamma*(h1@W2+b2)        12.8 MB
__device__ __half g_y16[(size_t)NN * OUTC];   // propagation state        6.4 MB
__device__ __half g_atz16[(size_t)NN * OUTC]; // scatter accum (fp16)     6.4 MB
__device__ __half g_zh[(size_t)EE * OUTC];    // edge dual vars (fp16)  102.4 MB
__device__ int2   g_rc[EE];                   // packed row,col
__device__ float  g_deg[NN];                  // deg -> rsqrt in place
__device__ int    g_is64;                     // edge_index dtype flag

// ---------------- helpers ---------------------------------------------------
__device__ __forceinline__ float clip1(float v) {
    return fminf(fmaxf(v, -LAM1), LAM1);
}

// 8-channel fp16 reduction: one 16B L2 atomic (4x f16x2)
__device__ __forceinline__ void redh8(__half* p, __half2 a, __half2 b,
                                      __half2 c, __half2 d) {
    asm volatile("red.global.add.noftz.v4.f16x2 [%0], {%1,%2,%3,%4};"
                 :: "l"(p),
                    "r"(*(uint32_t*)&a), "r"(*(uint32_t*)&b),
                    "r"(*(uint32_t*)&c), "r"(*(uint32_t*)&d) : "memory");
}

__device__ __forceinline__ void mma_tf32(float* c, const uint32_t* a, const uint32_t* b) {
    asm volatile(
        "mma.sync.aligned.m16n8k8.row.col.f32.tf32.tf32.f32 "
        "{%0,%1,%2,%3}, {%4,%5,%6,%7}, {%8,%9}, {%0,%1,%2,%3};"
        : "+f"(c[0]), "+f"(c[1]), "+f"(c[2]), "+f"(c[3])
        : "r"(a[0]), "r"(a[1]), "r"(a[2]), "r"(a[3]), "r"(b[0]), "r"(b[1]));
}

// ---------------- dtype detection -------------------------------------------
__global__ void k_detect(const unsigned* __restrict__ w) {
    __shared__ int nz;
    if (threadIdx.x == 0) nz = 0;
    __syncthreads();
    for (int j = threadIdx.x; j < 1024; j += 256)
        if (w[2 * j + 1] != 0u) atomicOr(&nz, 1);
    __syncthreads();
    if (threadIdx.x == 0) g_is64 = (nz == 0) ? 1 : 0;
}

// ---------------- precompute kernels ----------------------------------------
__global__ void k_zero_deg() {
    int i = blockIdx.x * blockDim.x + threadIdx.x;
    if (i < NN) g_deg[i] = 0.0f;
}

__global__ void k_prep_edges(const void* __restrict__ ei) {
    int e = blockIdx.x * blockDim.x + threadIdx.x;
    if (e >= EE) return;
    int r, c;
    if (g_is64) {
        const long long* p = (const long long*)ei;
        r = (int)p[e];
        c = (int)p[(size_t)EE + e];
    } else {
        const int* p = (const int*)ei;
        r = p[e];
        c = p[(size_t)EE + e];
    }
    r = min(max(r, 0), NN - 1);
    c = min(max(c, 0), NN - 1);
    g_rc[e] = make_int2(r, c);
    atomicAdd(&g_deg[r], 1.0f);
    atomicAdd(&g_deg[c], 1.0f);
}

__global__ void k_dis() {
    int i = blockIdx.x * blockDim.x + threadIdx.x;
    if (i < NN) g_deg[i] = rsqrtf(fmaxf(g_deg[i], 1.0f));
}

__global__ void k_zero_atz() {
    int i = blockIdx.x * blockDim.x + threadIdx.x;   // NN*OUTC/8 = 400000
    if (i < NN * OUTC / 8)
        ((uint4*)g_atz16)[i] = make_uint4(0u, 0u, 0u, 0u);
}

// ---------------- GEMM1 (tf32 tensor-core): h1 = relu(x @ W1 + b1) ----------
// Raw fp32 stored in SMEM; mma.sync truncates to tf32 in hardware (RZ).
__global__ void __launch_bounds__(256, 2)
k_gemm1(const float* __restrict__ x, const float* __restrict__ W1,
        const float* __restrict__ b1) {
    __shared__ __align__(16) float As[2][128][20];   // [buf][m][k]
    __shared__ __align__(16) float Bs[2][16][136];   // [buf][k][n]

    const int t    = threadIdx.x;
    const int bn   = blockIdx.x * 128;
    const int bm   = blockIdx.y * 128;
    const int lane = t & 31;
    const int warp = t >> 5;
    const int wm   = (warp & 1) * 64;
    const int wn   = (warp >> 1) * 32;
    const int lr   = lane >> 2;
    const int lc   = lane & 3;

    const int am0 = t >> 2,        akf = (t & 3) * 4;
    const int am1 = (t + 256) >> 2;
    const int bk0 = t >> 5,        bnf = (t & 31) * 4;
    const int bk1 = (t + 256) >> 5;

    float acc[4][4][4];
#pragma unroll
    for (int mi = 0; mi < 4; mi++)
#pragma unroll
        for (int ni = 0; ni < 4; ni++)
#pragma unroll
            for (int r = 0; r < 4; r++) acc[mi][ni][r] = 0.0f;

    {
        float4 va0 = make_float4(0.f,0.f,0.f,0.f), va1 = va0;
        if (bm + am0 < NN) va0 = *(const float4*)(x + (size_t)(bm + am0) * INC + akf);
        if (bm + am1 < NN) va1 = *(const float4*)(x + (size_t)(bm + am1) * INC + akf);
        float4 vb0 = *(const float4*)(W1 + (size_t)bk0 * HIDC + bn + bnf);
        float4 vb1 = *(const float4*)(W1 + (size_t)bk1 * HIDC + bn + bnf);
        As[0][am0][akf+0] = va0.x;  As[0][am0][akf+1] = va0.y;
        As[0][am0][akf+2] = va0.z;  As[0][am0][akf+3] = va0.w;
        As[0][am1][akf+0] = va1.x;  As[0][am1][akf+1] = va1.y;
        As[0][am1][akf+2] = va1.z;  As[0][am1][akf+3] = va1.w;
        *(float4*)&Bs[0][bk0][bnf] = vb0;
        *(float4*)&Bs[0][bk1][bnf] = vb1;
    }
    __syncthreads();

    const int NIT = INC / 16;   // 32
    float4 pa0, pa1, pb0, pb1;

    for (int it = 0; it < NIT; it++) {
        const int buf = it & 1;

        if (it + 1 < NIT) {
            int k0 = (it + 1) * 16;
            pa0 = make_float4(0.f,0.f,0.f,0.f); pa1 = pa0;
            if (bm + am0 < NN) pa0 = *(const float4*)(x + (size_t)(bm + am0) * INC + k0 + akf);
            if (bm + am1 < NN) pa1 = *(const float4*)(x + (size_t)(bm + am1) * INC + k0 + akf);
            pb0 = *(const float4*)(W1 + (size_t)(k0 + bk0) * HIDC + bn + bnf);
            pb1 = *(const float4*)(W1 + (size_t)(k0 + bk1) * HIDC + bn + bnf);
        }

#pragma unroll
        for (int ki = 0; ki < 2; ki++) {
            const int kb = ki * 8;
            uint32_t a[4][4], b[4][2];
#pragma unroll
            for (int mi = 0; mi < 4; mi++) {
                const int m0 = wm + mi * 16 + lr;
                const int kk = kb + lc;
                a[mi][0] = __float_as_uint(As[buf][m0    ][kk    ]);
                a[mi][1] = __float_as_uint(As[buf][m0 + 8][kk    ]);
                a[mi][2] = __float_as_uint(As[buf][m0    ][kk + 4]);
                a[mi][3] = __float_as_uint(As[buf][m0 + 8][kk + 4]);
            }
#pragma unroll
            for (int ni = 0; ni < 4; ni++) {
                const int n0 = wn + ni * 8 + lr;
                const int kk = kb + lc;
                b[ni][0] = __float_as_uint(Bs[buf][kk    ][n0]);
                b[ni][1] = __float_as_uint(Bs[buf][kk + 4][n0]);
            }
#pragma unroll
            for (int mi = 0; mi < 4; mi++)
#pragma unroll
                for (int ni = 0; ni < 4; ni++)
                    mma_tf32(acc[mi][ni], a[mi], b[ni]);
        }

        if (it + 1 < NIT) {
            const int nb = buf ^ 1;
            As[nb][am0][akf+0] = pa0.x;  As[nb][am0][akf+1] = pa0.y;
            As[nb][am0][akf+2] = pa0.z;  As[nb][am0][akf+3] = pa0.w;
            As[nb][am1][akf+0] = pa1.x;  As[nb][am1][akf+1] = pa1.y;
            As[nb][am1][akf+2] = pa1.z;  As[nb][am1][akf+3] = pa1.w;
            *(float4*)&Bs[nb][bk0][bnf] = pb0;
            *(float4*)&Bs[nb][bk1][bnf] = pb1;
            __syncthreads();
        }
    }

#pragma unroll
    for (int mi = 0; mi < 4; mi++) {
        const int r0 = bm + wm + mi * 16 + lr;
#pragma unroll
        for (int ni = 0; ni < 4; ni++) {
            const int col = bn + wn + ni * 8 + 2 * lc;
            const float bx = b1[col], by = b1[col + 1];
            if (r0 < NN) {
                float2 v;
                v.x = fmaxf(acc[mi][ni][0] + bx, 0.f);
                v.y = fmaxf(acc[mi][ni][1] + by, 0.f);
                *(float2*)(g_h1 + (size_t)r0 * HIDC + col) = v;
            }
            if (r0 + 8 < NN) {
                float2 v;
                v.x = fmaxf(acc[mi][ni][2] + bx, 0.f);
                v.y = fmaxf(acc[mi][ni][3] + by, 0.f);
                *(float2*)(g_h1 + (size_t)(r0 + 8) * HIDC + col) = v;
            }
        }
    }
}

// ---------------- GEMM2: hg = gamma*(h1 @ W2 + b2); y16 = hg ----------------
__global__ void __launch_bounds__(256)
k_gemm2(const float* __restrict__ W2, const float* __restrict__ b2) {
    __shared__ float W2s[HIDC * OUTC];   // 32 KB
    const int t = threadIdx.x;
    for (int i = t; i < HIDC * OUTC / 4; i += 256)
        ((float4*)W2s)[i] = ((const float4*)W2)[i];
    __syncthreads();

    const int warp = t >> 5, lane = t & 31;
    const int row0 = blockIdx.x * 32 + warp * 4;

    float bias = b2[lane];
    float acc[4] = {bias, bias, bias, bias};

    const float4* h0  = (const float4*)(g_h1 + (size_t)(row0 + 0) * HIDC);
    const float4* h1p = (const float4*)(g_h1 + (size_t)(row0 + 1) * HIDC);
    const float4* h2p = (const float4*)(g_h1 + (size_t)(row0 + 2) * HIDC);
    const float4* h3p = (const float4*)(g_h1 + (size_t)(row0 + 3) * HIDC);

#pragma unroll 8
    for (int k4 = 0; k4 < HIDC / 4; k4++) {
        float w0 = W2s[(k4 * 4 + 0) * OUTC + lane];
        float w1 = W2s[(k4 * 4 + 1) * OUTC + lane];
        float w2 = W2s[(k4 * 4 + 2) * OUTC + lane];
        float w3 = W2s[(k4 * 4 + 3) * OUTC + lane];
        float4 h;
        h = h0[k4];  acc[0] = fmaf(h.x,w0, fmaf(h.y,w1, fmaf(h.z,w2, fmaf(h.w,w3, acc[0]))));
        h = h1p[k4]; acc[1] = fmaf(h.x,w0, fmaf(h.y,w1, fmaf(h.z,w2, fmaf(h.w,w3, acc[1]))));
        h = h2p[k4]; acc[2] = fmaf(h.x,w0, fmaf(h.y,w1, fmaf(h.z,w2, fmaf(h.w,w3, acc[2]))));
        h = h3p[k4]; acc[3] = fmaf(h.x,w0, fmaf(h.y,w1, fmaf(h.z,w2, fmaf(h.w,w3, acc[3]))));
    }
#pragma unroll
    for (int r = 0; r < 4; r++) {
        float v = GAMMA * acc[r];
        size_t idx = (size_t)(row0 + r) * OUTC + lane;
        g_hg[idx]  = v;
        g_y16[idx] = __float2half_rn(v);   // y0 = gamma*h
    }
}

// ---------------- EMP edge kernel -------------------------------------------
// 2 threads per edge, 16 channels each. y gathered fp16, z streamed fp16 with
// L1 bypass (no store on the last iteration — never read again). Scatter into
// fp16 atz via red.global.add.v4.f16x2.
template <bool FIRST, bool LAST>
__global__ void __launch_bounds__(256)
k_edge() {
    unsigned tid = blockIdx.x * blockDim.x + threadIdx.x;
    if (tid >= (unsigned)EE * 2u) return;
    int e   = tid >> 1;
    int off = (tid & 1) * 16;

    int2  rc  = __ldg(&g_rc[e]);
    float dre = __ldg(&g_deg[rc.x]);
    float dce = __ldg(&g_deg[rc.y]);

    const uint4* yr = (const uint4*)(g_y16 + (size_t)rc.x * OUTC + off);
    const uint4* yc = (const uint4*)(g_y16 + (size_t)rc.y * OUTC + off);
    uint4*       zp = (uint4*)(g_zh + (size_t)e * OUTC + off);
    __half*      ar = g_atz16 + (size_t)rc.x * OUTC + off;
    __half*      ac = g_atz16 + (size_t)rc.y * OUTC + off;

#pragma unroll
    for (int hh = 0; hh < 2; hh++) {
        uint4 yru = __ldg(yr + hh);
        uint4 ycu = __ldg(yc + hh);
        float2 a01 = __half22float2(*(__half2*)&yru.x);
        float2 a23 = __half22float2(*(__half2*)&yru.y);
        float2 a45 = __half22float2(*(__half2*)&yru.z);
        float2 a67 = __half22float2(*(__half2*)&yru.w);
        float2 b01 = __half22float2(*(__half2*)&ycu.x);
        float2 b23 = __half22float2(*(__half2*)&ycu.y);
        float2 b45 = __half22float2(*(__half2*)&ycu.z);
        float2 b67 = __half22float2(*(__half2*)&ycu.w);

        float2 zf[4];
        if (FIRST) {
            zf[0] = zf[1] = zf[2] = zf[3] = make_float2(0.f, 0.f);
        } else {
            uint4 zr = __ldcg(zp + hh);
            zf[0] = __half22float2(*(__half2*)&zr.x);
            zf[1] = __half22float2(*(__half2*)&zr.y);
            zf[2] = __half22float2(*(__half2*)&zr.z);
            zf[3] = __half22float2(*(__half2*)&zr.w);
        }

        float z0 = clip1(fmaf(BETA, a01.x * dre - b01.x * dce, zf[0].x));
        float z1 = clip1(fmaf(BETA, a01.y * dre - b01.y * dce, zf[0].y));
        float z2 = clip1(fmaf(BETA, a23.x * dre - b23.x * dce, zf[1].x));
        float z3 = clip1(fmaf(BETA, a23.y * dre - b23.y * dce, zf[1].y));
        float z4 = clip1(fmaf(BETA, a45.x * dre - b45.x * dce, zf[2].x));
        float z5 = clip1(fmaf(BETA, a45.y * dre - b45.y * dce, zf[2].y));
        float z6 = clip1(fmaf(BETA, a67.x * dre - b67.x * dce, zf[3].x));
        float z7 = clip1(fmaf(BETA, a67.y * dre - b67.y * dce, zf[3].y));

        __half2 p0 = __floats2half2_rn(z0, z1);
        __half2 p1 = __floats2half2_rn(z2, z3);
        __half2 p2 = __floats2half2_rn(z4, z5);
        __half2 p3 = __floats2half2_rn(z6, z7);
        if (!LAST) {
            uint4 zw;
            zw.x = *(uint32_t*)&p0; zw.y = *(uint32_t*)&p1;
            zw.z = *(uint32_t*)&p2; zw.w = *(uint32_t*)&p3;
            __stcg(zp + hh, zw);
        }

        float2 q0 = __half22float2(p0), q1 = __half22float2(p1);
        float2 q2 = __half22float2(p2), q3 = __half22float2(p3);

        redh8(ar + hh * 8,
              __floats2half2_rn(q0.x * dre, q0.y * dre),
              __floats2half2_rn(q1.x * dre, q1.y * dre),
              __floats2half2_rn(q2.x * dre, q2.y * dre),
              __floats2half2_rn(q3.x * dre, q3.y * dre));
        redh8(ac + hh * 8,
              __floats2half2_rn(-q0.x * dce, -q0.y * dce),
              __floats2half2_rn(-q1.x * dce, -q1.y * dce),
              __floats2half2_rn(-q2.x * dce, -q2.y * dce),
              __floats2half2_rn(-q3.x * dce, -q3.y * dce));
    }
}

// ---------------- EMP node kernel: y16 = hg - gamma*atz16; atz16 = 0 ---------
__global__ void k_node() {
    int i = blockIdx.x * blockDim.x + threadIdx.x;   // 400000 (8 ch each)
    if (i >= NN * OUTC / 8) return;
    float4 h0 = ((const float4*)g_hg)[2 * i];
    float4 h1 = ((const float4*)g_hg)[2 * i + 1];
    uint4  au = ((const uint4*)g_atz16)[i];
    float2 a01 = __half22float2(*(__half2*)&au.x);
    float2 a23 = __half22float2(*(__half2*)&au.y);
    float2 a45 = __half22float2(*(__half2*)&au.z);
    float2 a67 = __half22float2(*(__half2*)&au.w);

    __half2 p0 = __floats2half2_rn(fmaf(-GAMMA, a01.x, h0.x), fmaf(-GAMMA, a01.y, h0.y));
    __half2 p1 = __floats2half2_rn(fmaf(-GAMMA, a23.x, h0.z), fmaf(-GAMMA, a23.y, h0.w));
    __half2 p2 = __floats2half2_rn(fmaf(-GAMMA, a45.x, h1.x), fmaf(-GAMMA, a45.y, h1.y));
    __half2 p3 = __floats2half2_rn(fmaf(-GAMMA, a67.x, h1.z), fmaf(-GAMMA, a67.y, h1.w));
    uint4 yw;
    yw.x = *(uint32_t*)&p0; yw.y = *(uint32_t*)&p1;
    yw.z = *(uint32_t*)&p2; yw.w = *(uint32_t*)&p3;
    ((uint4*)g_y16)[i] = yw;

    ((uint4*)g_atz16)[i] = make_uint4(0u, 0u, 0u, 0u);
}

// ---------------- fused final node + log_softmax -----------------------------
__global__ void k_node_lsm(float* __restrict__ out) {
    int i = blockIdx.x * blockDim.x + threadIdx.x;
    if (i >= NN) return;
    const float4* hp = (const float4*)(g_hg + (size_t)i * OUTC);
    const uint4*  ap = (const uint4*)(g_atz16 + (size_t)i * OUTC);
    float4 v[8];
#pragma unroll
    for (int k = 0; k < 4; k++) {
        uint4 au = ap[k];
        float2 a01 = __half22float2(*(__half2*)&au.x);
        float2 a23 = __half22float2(*(__half2*)&au.y);
        float2 a45 = __half22float2(*(__half2*)&au.z);
        float2 a67 = __half22float2(*(__half2*)&au.w);
        float4 h0 = hp[2 * k], h1 = hp[2 * k + 1];
        v[2*k].x   = fmaf(-GAMMA, a01.x, h0.x);
        v[2*k].y   = fmaf(-GAMMA, a01.y, h0.y);
        v[2*k].z   = fmaf(-GAMMA, a23.x, h0.z);
        v[2*k].w   = fmaf(-GAMMA, a23.y, h0.w);
        v[2*k+1].x = fmaf(-GAMMA, a45.x, h1.x);
        v[2*k+1].y = fmaf(-GAMMA, a45.y, h1.y);
        v[2*k+1].z = fmaf(-GAMMA, a67.x, h1.z);
        v[2*k+1].w = fmaf(-GAMMA, a67.y, h1.w);
    }

    float m = -3.4e38f;
#pragma unroll
    for (int k = 0; k < 8; k++)
        m = fmaxf(m, fmaxf(fmaxf(v[k].x, v[k].y), fmaxf(v[k].z, v[k].w)));
    float s = 0.f;
#pragma unroll
    for (int k = 0; k < 8; k++)
        s += expf(v[k].x - m) + expf(v[k].y - m) + expf(v[k].z - m) + expf(v[k].w - m);
    float l = m + logf(s);

    float4* op = (float4*)(out + (size_t)i * OUTC);
#pragma unroll
    for (int k = 0; k < 8; k++) {
        float4 o;
        o.x = v[k].x - l; o.y = v[k].y - l; o.z = v[k].z - l; o.w = v[k].w - l;
        op[k] = o;
    }
}

// ---------------- launch ------------------------------------------------------
extern "C" void kernel_launch(void* const* d_in, const int* in_sizes, int n_in,
                              void* d_out, int out_size) {
    const float* x   = (const float*)d_in[0];
    const void*  ei  = d_in[1];                 // int32 or int64, detected on device
    const float* W1  = (const float*)d_in[2];
    const float* b1  = (const float*)d_in[3];
    const float* W2  = (const float*)d_in[4];
    const float* b2  = (const float*)d_in[5];
    float*       out = (float*)d_out;

    // edge/degree preprocessing
    k_detect<<<1, 256>>>((const unsigned*)ei);
    k_zero_deg<<<(NN + 255) / 256, 256>>>();
    k_prep_edges<<<EE / 256, 256>>>(ei);
    k_dis<<<(NN + 255) / 256, 256>>>();

    // MLP
    k_gemm1<<<dim3(HIDC / 128, (NN + 127) / 128), 256>>>(x, W1, b1);
    k_gemm2<<<NN / 32, 256>>>(W2, b2);
    k_zero_atz<<<(NN * OUTC / 8 + 255) / 256, 256>>>();

    // elastic message passing, K = 5 (last node step fused with log_softmax;
    // last edge iteration skips the z store)
    const int EG = (EE * 2) / 256;   // 12500 blocks, exact
    k_edge<true,  false><<<EG, 256>>>();
    k_node<<<(NN * OUTC / 8 + 255) / 256, 256>>>();
    for (int t = 1; t < KIT - 1; t++) {
        k_edge<false, false><<<EG, 256>>>();
        k_node<<<(NN * OUTC / 8 + 255) / 256, 256>>>();
    }
    k_edge<false, true><<<EG, 256>>>();
    k_node_lsm<<<(NN + 255) / 256, 256>>>(out);
}

// round 17
// speedup vs baseline: 1.2032x; 1.2032x over previous
#include <cuda_runtime.h>
#include <cuda_fp16.h>
#include <cstdint>
#include <cstddef>

// Problem constants
#define NN    100000
#define INC   512
#define HIDC  256
#define OUTC  32
#define EE    1600000
#define KIT   5
#define LAM1  3.0f
#define GAMMA 0.25f      // 1/(1+LAM2), LAM2=3
#define BETA  2.0f       // 1/(2*GAMMA)

// ---------------- device scratch (static: no allocations allowed) ----------
__device__ float  g_h1[(size_t)NN * HIDC];    // relu(x@W1+b1)          102.4 MB
__device__ float  g_hg[(size_t)NN * OUTC];    // gamma*(h1@W2+b2)        12.8 MB
__device__ __half g_y16[(size_t)NN * OUTC];   // propagation state        6.4 MB
__device__ __half g_atz16[(size_t)NN * OUTC]; // scatter accum (fp16)     6.4 MB
__device__ __half g_zh[(size_t)EE * OUTC];    // edge dual vars (fp16)  102.4 MB
__device__ int2   g_rc[EE];                   // packed row,col
__device__ float  g_deg[NN];                  // deg -> rsqrt in place
__device__ int    g_is64;                     // edge_index dtype flag

// ---------------- helpers ---------------------------------------------------
__device__ __forceinline__ float clip1(float v) {
    return fminf(fmaxf(v, -LAM1), LAM1);
}

// 8-channel fp16 reduction: one 16B L2 atomic (4x f16x2)
__device__ __forceinline__ void redh8(__half* p, __half2 a, __half2 b,
                                      __half2 c, __half2 d) {
    asm volatile("red.global.add.noftz.v4.f16x2 [%0], {%1,%2,%3,%4};"
                 :: "l"(p),
                    "r"(*(uint32_t*)&a), "r"(*(uint32_t*)&b),
                    "r"(*(uint32_t*)&c), "r"(*(uint32_t*)&d) : "memory");
}

__device__ __forceinline__ void mma_tf32(float* c, const uint32_t* a, const uint32_t* b) {
    asm volatile(
        "mma.sync.aligned.m16n8k8.row.col.f32.tf32.tf32.f32 "
        "{%0,%1,%2,%3}, {%4,%5,%6,%7}, {%8,%9}, {%0,%1,%2,%3};"
        : "+f"(c[0]), "+f"(c[1]), "+f"(c[2]), "+f"(c[3])
        : "r"(a[0]), "r"(a[1]), "r"(a[2]), "r"(a[3]), "r"(b[0]), "r"(b[1]));
}

// ---------------- dtype detection -------------------------------------------
__global__ void k_detect(const unsigned* __restrict__ w) {
    __shared__ int nz;
    if (threadIdx.x == 0) nz = 0;
    __syncthreads();
    for (int j = threadIdx.x; j < 1024; j += 256)
        if (w[2 * j + 1] != 0u) atomicOr(&nz, 1);
    __syncthreads();
    if (threadIdx.x == 0) g_is64 = (nz == 0) ? 1 : 0;
}

// ---------------- precompute kernels ----------------------------------------
__global__ void k_zero_deg() {
    int i = blockIdx.x * blockDim.x + threadIdx.x;
    if (i < NN) g_deg[i] = 0.0f;
}

__global__ void k_prep_edges(const void* __restrict__ ei) {
    int e = blockIdx.x * blockDim.x + threadIdx.x;
    if (e >= EE) return;
    int r, c;
    if (g_is64) {
        const long long* p = (const long long*)ei;
        r = (int)p[e];
        c = (int)p[(size_t)EE + e];
    } else {
        const int* p = (const int*)ei;
        r = p[e];
        c = p[(size_t)EE + e];
    }
    r = min(max(r, 0), NN - 1);
    c = min(max(c, 0), NN - 1);
    g_rc[e] = make_int2(r, c);
    atomicAdd(&g_deg[r], 1.0f);
    atomicAdd(&g_deg[c], 1.0f);
}

__global__ void k_dis() {
    int i = blockIdx.x * blockDim.x + threadIdx.x;
    if (i < NN) g_deg[i] = rsqrtf(fmaxf(g_deg[i], 1.0f));
}

__global__ void k_zero_atz() {
    int i = blockIdx.x * blockDim.x + threadIdx.x;   // NN*OUTC/8 = 400000
    if (i < NN * OUTC / 8)
        ((uint4*)g_atz16)[i] = make_uint4(0u, 0u, 0u, 0u);
}

// ---------------- GEMM1 (tf32 tensor-core): h1 = relu(x @ W1 + b1) ----------
// Raw fp32 stored in SMEM; mma.sync truncates to tf32 in hardware.
__global__ void __launch_bounds__(256, 2)
k_gemm1(const float* __restrict__ x, const float* __restrict__ W1,
        const float* __restrict__ b1) {
    __shared__ __align__(16) float As[2][128][20];   // [buf][m][k]
    __shared__ __align__(16) float Bs[2][16][136];   // [buf][k][n]

    const int t    = threadIdx.x;
    const int bn   = blockIdx.x * 128;
    const int bm   = blockIdx.y * 128;
    const int lane = t & 31;
    const int warp = t >> 5;
    const int wm   = (warp & 1) * 64;
    const int wn   = (warp >> 1) * 32;
    const int lr   = lane >> 2;
    const int lc   = lane & 3;

    const int am0 = t >> 2,        akf = (t & 3) * 4;
    const int am1 = (t + 256) >> 2;
    const int bk0 = t >> 5,        bnf = (t & 31) * 4;
    const int bk1 = (t + 256) >> 5;

    float acc[4][4][4];
#pragma unroll
    for (int mi = 0; mi < 4; mi++)
#pragma unroll
        for (int ni = 0; ni < 4; ni++)
#pragma unroll
            for (int r = 0; r < 4; r++) acc[mi][ni][r] = 0.0f;

    {
        float4 va0 = make_float4(0.f,0.f,0.f,0.f), va1 = va0;
        if (bm + am0 < NN) va0 = *(const float4*)(x + (size_t)(bm + am0) * INC + akf);
        if (bm + am1 < NN) va1 = *(const float4*)(x + (size_t)(bm + am1) * INC + akf);
        float4 vb0 = *(const float4*)(W1 + (size_t)bk0 * HIDC + bn + bnf);
        float4 vb1 = *(const float4*)(W1 + (size_t)bk1 * HIDC + bn + bnf);
        As[0][am0][akf+0] = va0.x;  As[0][am0][akf+1] = va0.y;
        As[0][am0][akf+2] = va0.z;  As[0][am0][akf+3] = va0.w;
        As[0][am1][akf+0] = va1.x;  As[0][am1][akf+1] = va1.y;
        As[0][am1][akf+2] = va1.z;  As[0][am1][akf+3] = va1.w;
        *(float4*)&Bs[0][bk0][bnf] = vb0;
        *(float4*)&Bs[0][bk1][bnf] = vb1;
    }
    __syncthreads();

    const int NIT = INC / 16;   // 32
    float4 pa0, pa1, pb0, pb1;

    for (int it = 0; it < NIT; it++) {
        const int buf = it & 1;

        if (it + 1 < NIT) {
            int k0 = (it + 1) * 16;
            pa0 = make_float4(0.f,0.f,0.f,0.f); pa1 = pa0;
            if (bm + am0 < NN) pa0 = *(const float4*)(x + (size_t)(bm + am0) * INC + k0 + akf);
            if (bm + am1 < NN) pa1 = *(const float4*)(x + (size_t)(bm + am1) * INC + k0 + akf);
            pb0 = *(const float4*)(W1 + (size_t)(k0 + bk0) * HIDC + bn + bnf);
            pb1 = *(const float4*)(W1 + (size_t)(k0 + bk1) * HIDC + bn + bnf);
        }

#pragma unroll
        for (int ki = 0; ki < 2; ki++) {
            const int kb = ki * 8;
            uint32_t a[4][4], b[4][2];
#pragma unroll
            for (int mi = 0; mi < 4; mi++) {
                const int m0 = wm + mi * 16 + lr;
                const int kk = kb + lc;
                a[mi][0] = __float_as_uint(As[buf][m0    ][kk    ]);
                a[mi][1] = __float_as_uint(As[buf][m0 + 8][kk    ]);
                a[mi][2] = __float_as_uint(As[buf][m0    ][kk + 4]);
                a[mi][3] = __float_as_uint(As[buf][m0 + 8][kk + 4]);
            }
#pragma unroll
            for (int ni = 0; ni < 4; ni++) {
                const int n0 = wn + ni * 8 + lr;
                const int kk = kb + lc;
                b[ni][0] = __float_as_uint(Bs[buf][kk    ][n0]);
                b[ni][1] = __float_as_uint(Bs[buf][kk + 4][n0]);
            }
#pragma unroll
            for (int mi = 0; mi < 4; mi++)
#pragma unroll
                for (int ni = 0; ni < 4; ni++)
                    mma_tf32(acc[mi][ni], a[mi], b[ni]);
        }

        if (it + 1 < NIT) {
            const int nb = buf ^ 1;
            As[nb][am0][akf+0] = pa0.x;  As[nb][am0][akf+1] = pa0.y;
            As[nb][am0][akf+2] = pa0.z;  As[nb][am0][akf+3] = pa0.w;
            As[nb][am1][akf+0] = pa1.x;  As[nb][am1][akf+1] = pa1.y;
            As[nb][am1][akf+2] = pa1.z;  As[nb][am1][akf+3] = pa1.w;
            *(float4*)&Bs[nb][bk0][bnf] = pb0;
            *(float4*)&Bs[nb][bk1][bnf] = pb1;
            __syncthreads();
        }
    }

#pragma unroll
    for (int mi = 0; mi < 4; mi++) {
        const int r0 = bm + wm + mi * 16 + lr;
#pragma unroll
        for (int ni = 0; ni < 4; ni++) {
            const int col = bn + wn + ni * 8 + 2 * lc;
            const float bx = b1[col], by = b1[col + 1];
            if (r0 < NN) {
                float2 v;
                v.x = fmaxf(acc[mi][ni][0] + bx, 0.f);
                v.y = fmaxf(acc[mi][ni][1] + by, 0.f);
                *(float2*)(g_h1 + (size_t)r0 * HIDC + col) = v;
            }
            if (r0 + 8 < NN) {
                float2 v;
                v.x = fmaxf(acc[mi][ni][2] + bx, 0.f);
                v.y = fmaxf(acc[mi][ni][3] + by, 0.f);
                *(float2*)(g_h1 + (size_t)(r0 + 8) * HIDC + col) = v;
            }
        }
    }
}

// ---------------- GEMM2: hg = gamma*(h1 @ W2 + b2); y16 = hg ----------------
__global__ void __launch_bounds__(256)
k_gemm2(const float* __restrict__ W2, const float* __restrict__ b2) {
    __shared__ float W2s[HIDC * OUTC];   // 32 KB
    const int t = threadIdx.x;
    for (int i = t; i < HIDC * OUTC / 4; i += 256)
        ((float4*)W2s)[i] = ((const float4*)W2)[i];
    __syncthreads();

    const int warp = t >> 5, lane = t & 31;
    const int row0 = blockIdx.x * 32 + warp * 4;

    float bias = b2[lane];
    float acc[4] = {bias, bias, bias, bias};

    const float4* h0  = (const float4*)(g_h1 + (size_t)(row0 + 0) * HIDC);
    const float4* h1p = (const float4*)(g_h1 + (size_t)(row0 + 1) * HIDC);
    const float4* h2p = (const float4*)(g_h1 + (size_t)(row0 + 2) * HIDC);
    const float4* h3p = (const float4*)(g_h1 + (size_t)(row0 + 3) * HIDC);

#pragma unroll 8
    for (int k4 = 0; k4 < HIDC / 4; k4++) {
        float w0 = W2s[(k4 * 4 + 0) * OUTC + lane];
        float w1 = W2s[(k4 * 4 + 1) * OUTC + lane];
        float w2 = W2s[(k4 * 4 + 2) * OUTC + lane];
        float w3 = W2s[(k4 * 4 + 3) * OUTC + lane];
        float4 h;
        h = h0[k4];  acc[0] = fmaf(h.x,w0, fmaf(h.y,w1, fmaf(h.z,w2, fmaf(h.w,w3, acc[0]))));
        h = h1p[k4]; acc[1] = fmaf(h.x,w0, fmaf(h.y,w1, fmaf(h.z,w2, fmaf(h.w,w3, acc[1]))));
        h = h2p[k4]; acc[2] = fmaf(h.x,w0, fmaf(h.y,w1, fmaf(h.z,w2, fmaf(h.w,w3, acc[2]))));
        h = h3p[k4]; acc[3] = fmaf(h.x,w0, fmaf(h.y,w1, fmaf(h.z,w2, fmaf(h.w,w3, acc[3]))));
    }
#pragma unroll
    for (int r = 0; r < 4; r++) {
        float v = GAMMA * acc[r];
        size_t idx = (size_t)(row0 + r) * OUTC + lane;
        g_hg[idx]  = v;
        g_y16[idx] = __float2half_rn(v);   // y0 = gamma*h
    }
}

// ---------------- EMP edge kernel -------------------------------------------
// 4 threads per edge, 8 channels each (R15 structure — max TLP). y gathered
// fp16 (16B), z streamed fp16 with L1 bypass (store skipped on last iter).
// Scatter into fp16 atz via red.global.add.v4.f16x2.
template <bool FIRST, bool LAST>
__global__ void __launch_bounds__(256)
k_edge() {
    unsigned tid = blockIdx.x * blockDim.x + threadIdx.x;
    if (tid >= (unsigned)EE * 4u) return;
    int e   = tid >> 2;
    int off = (tid & 3) * 8;

    int2  rc  = __ldg(&g_rc[e]);
    float dre = __ldg(&g_deg[rc.x]);
    float dce = __ldg(&g_deg[rc.y]);

    uint4 yru = __ldg((const uint4*)(g_y16 + (size_t)rc.x * OUTC + off));
    uint4 ycu = __ldg((const uint4*)(g_y16 + (size_t)rc.y * OUTC + off));
    float2 a01 = __half22float2(*(__half2*)&yru.x);
    float2 a23 = __half22float2(*(__half2*)&yru.y);
    float2 a45 = __half22float2(*(__half2*)&yru.z);
    float2 a67 = __half22float2(*(__half2*)&yru.w);
    float2 b01 = __half22float2(*(__half2*)&ycu.x);
    float2 b23 = __half22float2(*(__half2*)&ycu.y);
    float2 b45 = __half22float2(*(__half2*)&ycu.z);
    float2 b67 = __half22float2(*(__half2*)&ycu.w);

    __half* zp = g_zh + (size_t)e * OUTC + off;   // 16B aligned
    float2 zf[4];
    if (FIRST) {
        zf[0] = zf[1] = zf[2] = zf[3] = make_float2(0.f, 0.f);
    } else {
        uint4 zr = __ldcg((const uint4*)zp);
        zf[0] = __half22float2(*(__half2*)&zr.x);
        zf[1] = __half22float2(*(__half2*)&zr.y);
        zf[2] = __half22float2(*(__half2*)&zr.z);
        zf[3] = __half22float2(*(__half2*)&zr.w);
    }

    float z0x = clip1(fmaf(BETA, a01.x * dre - b01.x * dce, zf[0].x));
    float z0y = clip1(fmaf(BETA, a01.y * dre - b01.y * dce, zf[0].y));
    float z0z = clip1(fmaf(BETA, a23.x * dre - b23.x * dce, zf[1].x));
    float z0w = clip1(fmaf(BETA, a23.y * dre - b23.y * dce, zf[1].y));
    float z1x = clip1(fmaf(BETA, a45.x * dre - b45.x * dce, zf[2].x));
    float z1y = clip1(fmaf(BETA, a45.y * dre - b45.y * dce, zf[2].y));
    float z1z = clip1(fmaf(BETA, a67.x * dre - b67.x * dce, zf[3].x));
    float z1w = clip1(fmaf(BETA, a67.y * dre - b67.y * dce, zf[3].y));

    // pack to fp16; scatter uses the ROUNDED values so stored state and
    // propagated values agree.
    __half2 p0 = __floats2half2_rn(z0x, z0y);
    __half2 p1 = __floats2half2_rn(z0z, z0w);
    __half2 p2 = __floats2half2_rn(z1x, z1y);
    __half2 p3 = __floats2half2_rn(z1z, z1w);
    if (!LAST) {
        uint4 zw;
        zw.x = *(uint32_t*)&p0; zw.y = *(uint32_t*)&p1;
        zw.z = *(uint32_t*)&p2; zw.w = *(uint32_t*)&p3;
        __stcg((uint4*)zp, zw);
    }

    float2 q0 = __half22float2(p0), q1 = __half22float2(p1);
    float2 q2 = __half22float2(p2), q3 = __half22float2(p3);

    __half* ar = g_atz16 + (size_t)rc.x * OUTC + off;
    __half* ac = g_atz16 + (size_t)rc.y * OUTC + off;
    redh8(ar,
          __floats2half2_rn(q0.x * dre, q0.y * dre),
          __floats2half2_rn(q1.x * dre, q1.y * dre),
          __floats2half2_rn(q2.x * dre, q2.y * dre),
          __floats2half2_rn(q3.x * dre, q3.y * dre));
    redh8(ac,
          __floats2half2_rn(-q0.x * dce, -q0.y * dce),
          __floats2half2_rn(-q1.x * dce, -q1.y * dce),
          __floats2half2_rn(-q2.x * dce, -q2.y * dce),
          __floats2half2_rn(-q3.x * dce, -q3.y * dce));
}

// ---------------- EMP node kernel: y16 = hg - gamma*atz16; atz16 = 0 ---------
__global__ void k_node() {
    int i = blockIdx.x * blockDim.x + threadIdx.x;   // 400000 (8 ch each)
    if (i >= NN * OUTC / 8) return;
    float4 h0 = ((const float4*)g_hg)[2 * i];
    float4 h1 = ((const float4*)g_hg)[2 * i + 1];
    uint4  au = ((const uint4*)g_atz16)[i];
    float2 a01 = __half22float2(*(__half2*)&au.x);
    float2 a23 = __half22float2(*(__half2*)&au.y);
    float2 a45 = __half22float2(*(__half2*)&au.z);
    float2 a67 = __half22float2(*(__half2*)&au.w);

    __half2 p0 = __floats2half2_rn(fmaf(-GAMMA, a01.x, h0.x), fmaf(-GAMMA, a01.y, h0.y));
    __half2 p1 = __floats2half2_rn(fmaf(-GAMMA, a23.x, h0.z), fmaf(-GAMMA, a23.y, h0.w));
    __half2 p2 = __floats2half2_rn(fmaf(-GAMMA, a45.x, h1.x), fmaf(-GAMMA, a45.y, h1.y));
    __half2 p3 = __floats2half2_rn(fmaf(-GAMMA, a67.x, h1.z), fmaf(-GAMMA, a67.y, h1.w));
    uint4 yw;
    yw.x = *(uint32_t*)&p0; yw.y = *(uint32_t*)&p1;
    yw.z = *(uint32_t*)&p2; yw.w = *(uint32_t*)&p3;
    ((uint4*)g_y16)[i] = yw;

    ((uint4*)g_atz16)[i] = make_uint4(0u, 0u, 0u, 0u);
}

// ---------------- fused final node + log_softmax -----------------------------
__global__ void k_node_lsm(float* __restrict__ out) {
    int i = blockIdx.x * blockDim.x + threadIdx.x;
    if (i >= NN) return;
    const float4* hp = (const float4*)(g_hg + (size_t)i * OUTC);
    const uint4*  ap = (const uint4*)(g_atz16 + (size_t)i * OUTC);
    float4 v[8];
#pragma unroll
    for (int k = 0; k < 4; k++) {
        uint4 au = ap[k];
        float2 a01 = __half22float2(*(__half2*)&au.x);
        float2 a23 = __half22float2(*(__half2*)&au.y);
        float2 a45 = __half22float2(*(__half2*)&au.z);
        float2 a67 = __half22float2(*(__half2*)&au.w);
        float4 h0 = hp[2 * k], h1 = hp[2 * k + 1];
        v[2*k].x   = fmaf(-GAMMA, a01.x, h0.x);
        v[2*k].y   = fmaf(-GAMMA, a01.y, h0.y);
        v[2*k].z   = fmaf(-GAMMA, a23.x, h0.z);
        v[2*k].w   = fmaf(-GAMMA, a23.y, h0.w);
        v[2*k+1].x = fmaf(-GAMMA, a45.x, h1.x);
        v[2*k+1].y = fmaf(-GAMMA, a45.y, h1.y);
        v[2*k+1].z = fmaf(-GAMMA, a67.x, h1.z);
        v[2*k+1].w = fmaf(-GAMMA, a67.y, h1.w);
    }

    float m = -3.4e38f;
#pragma unroll
    for (int k = 0; k < 8; k++)
        m = fmaxf(m, fmaxf(fmaxf(v[k].x, v[k].y), fmaxf(v[k].z, v[k].w)));
    float s = 0.f;
#pragma unroll
    for (int k = 0; k < 8; k++)
        s += expf(v[k].x - m) + expf(v[k].y - m) + expf(v[k].z - m) + expf(v[k].w - m);
    float l = m + logf(s);

    float4* op = (float4*)(out + (size_t)i * OUTC);
#pragma unroll
    for (int k = 0; k < 8; k++) {
        float4 o;
        o.x = v[k].x - l; o.y = v[k].y - l; o.z = v[k].z - l; o.w = v[k].w - l;
        op[k] = o;
    }
}

// ---------------- launch ------------------------------------------------------
extern "C" void kernel_launch(void* const* d_in, const int* in_sizes, int n_in,
                              void* d_out, int out_size) {
    const float* x   = (const float*)d_in[0];
    const void*  ei  = d_in[1];                 // int32 or int64, detected on device
    const float* W1  = (const float*)d_in[2];
    const float* b1  = (const float*)d_in[3];
    const float* W2  = (const float*)d_in[4];
    const float* b2  = (const float*)d_in[5];
    float*       out = (float*)d_out;

    // edge/degree preprocessing
    k_detect<<<1, 256>>>((const unsigned*)ei);
    k_zero_deg<<<(NN + 255) / 256, 256>>>();
    k_prep_edges<<<EE / 256, 256>>>(ei);
    k_dis<<<(NN + 255) / 256, 256>>>();

    // MLP
    k_gemm1<<<dim3(HIDC / 128, (NN + 127) / 128), 256>>>(x, W1, b1);
    k_gemm2<<<NN / 32, 256>>>(W2, b2);
    k_zero_atz<<<(NN * OUTC / 8 + 255) / 256, 256>>>();

    // elastic message passing, K = 5 (last node step fused with log_softmax;
    // last edge iteration skips the z store)
    const int EG = (EE * 4) / 256;   // 25000 blocks, exact
    k_edge<true,  false><<<EG, 256>>>();
    k_node<<<(NN * OUTC / 8 + 255) / 256, 256>>>();
    for (int t = 1; t < KIT - 1; t++) {
        k_edge<false, false><<<EG, 256>>>();
        k_node<<<(NN * OUTC / 8 + 255) / 256, 256>>>();
    }
    k_edge<false, true><<<EG, 256>>>();
    k_node_lsm<<<(NN + 255) / 256, 256>>>(out);
}